// round 1
// baseline (speedup 1.0000x reference)
#include <cuda_runtime.h>

// BarlowTwinsLoss: inputs e_q [16384,2048] f32, tau [16384,2048] f32 (row-major).
// loss = sum_d (1 - clip(corr_d, -1+eps, 1-eps))^2 where corr_d is the
// (N+eps)-normalized dot of the column-normalized (ddof=1 std) features.
//
// Strategy: one streaming pass computing per-column sufficient statistics
// {Se, St, See, Stt, Set}; deterministic tree reduction (no float atomics);
// fp64 finalize. HBM-bound: 256 MB mandatory traffic.

#define NROWS 16384
#define NCOLS 2048
#define ROW_BLOCKS 256
#define ROWS_PER_BLOCK (NROWS / ROW_BLOCKS)   // 64
#define COL_GROUPS 2
#define COLS_PER_GROUP (NCOLS / COL_GROUPS)   // 1024
#define THREADS 256                            // 256 threads * 4 cols = 1024 cols

// Scratch: 5 stats x 256 rowblocks x 2048 cols x 4B = 10.5 MB (static, no alloc)
__device__ float  g_partial[5][ROW_BLOCKS][NCOLS];
__device__ double g_stats[5][NCOLS];

// ---------------------------------------------------------------------------
// Kernel 1: streaming per-column partial sums. Each block: one 64-row slab of
// one 1024-column group. Thread t owns 4 consecutive columns (float4 loads,
// perfectly coalesced: warp covers 512 contiguous bytes per array per row).
// ---------------------------------------------------------------------------
__global__ void __launch_bounds__(THREADS)
stats_kernel(const float* __restrict__ e, const float* __restrict__ t)
{
    const int rb  = blockIdx.x;                       // row block
    const int col = blockIdx.y * COLS_PER_GROUP + threadIdx.x * 4;

    const float4* __restrict__ e4 =
        (const float4*)(e + (size_t)rb * ROWS_PER_BLOCK * NCOLS + col);
    const float4* __restrict__ t4 =
        (const float4*)(t + (size_t)rb * ROWS_PER_BLOCK * NCOLS + col);
    const int row_stride4 = NCOLS / 4;                // float4 stride per row

    float se0 = 0.f, se1 = 0.f, se2 = 0.f, se3 = 0.f;
    float st0 = 0.f, st1 = 0.f, st2 = 0.f, st3 = 0.f;
    float ee0 = 0.f, ee1 = 0.f, ee2 = 0.f, ee3 = 0.f;
    float tt0 = 0.f, tt1 = 0.f, tt2 = 0.f, tt3 = 0.f;
    float et0 = 0.f, et1 = 0.f, et2 = 0.f, et3 = 0.f;

    #pragma unroll 4
    for (int r = 0; r < ROWS_PER_BLOCK; ++r) {
        float4 a = e4[(size_t)r * row_stride4];
        float4 b = t4[(size_t)r * row_stride4];
        se0 += a.x; se1 += a.y; se2 += a.z; se3 += a.w;
        st0 += b.x; st1 += b.y; st2 += b.z; st3 += b.w;
        ee0 = fmaf(a.x, a.x, ee0); ee1 = fmaf(a.y, a.y, ee1);
        ee2 = fmaf(a.z, a.z, ee2); ee3 = fmaf(a.w, a.w, ee3);
        tt0 = fmaf(b.x, b.x, tt0); tt1 = fmaf(b.y, b.y, tt1);
        tt2 = fmaf(b.z, b.z, tt2); tt3 = fmaf(b.w, b.w, tt3);
        et0 = fmaf(a.x, b.x, et0); et1 = fmaf(a.y, b.y, et1);
        et2 = fmaf(a.z, b.z, et2); et3 = fmaf(a.w, b.w, et3);
    }

    ((float4*)&g_partial[0][rb][col])[0] = make_float4(se0, se1, se2, se3);
    ((float4*)&g_partial[1][rb][col])[0] = make_float4(st0, st1, st2, st3);
    ((float4*)&g_partial[2][rb][col])[0] = make_float4(ee0, ee1, ee2, ee3);
    ((float4*)&g_partial[3][rb][col])[0] = make_float4(tt0, tt1, tt2, tt3);
    ((float4*)&g_partial[4][rb][col])[0] = make_float4(et0, et1, et2, et3);
}

// ---------------------------------------------------------------------------
// Kernel 2: reduce 256 rowblock partials per (stat, column) in fp64.
// 5*2048 = 10240 threads; reads are coalesced across consecutive columns.
// ---------------------------------------------------------------------------
__global__ void __launch_bounds__(256)
reduce_kernel()
{
    const int g = blockIdx.x * blockDim.x + threadIdx.x;   // 0..10239
    if (g >= 5 * NCOLS) return;
    const int s   = g / NCOLS;
    const int col = g % NCOLS;
    double acc = 0.0;
    #pragma unroll 8
    for (int rb = 0; rb < ROW_BLOCKS; ++rb)
        acc += (double)g_partial[s][rb][col];
    g_stats[s][col] = acc;
}

// ---------------------------------------------------------------------------
// Kernel 3: finalize. One block; fp64 throughout; deterministic shared reduce.
// ---------------------------------------------------------------------------
__global__ void __launch_bounds__(256)
loss_kernel(float* __restrict__ out)
{
    __shared__ double red[256];
    const double N   = (double)NROWS;
    const double EPS = 1e-9;

    double loss = 0.0;
    for (int col = threadIdx.x; col < NCOLS; col += 256) {
        double Se  = g_stats[0][col];
        double St  = g_stats[1][col];
        double See = g_stats[2][col];
        double Stt = g_stats[3][col];
        double Set = g_stats[4][col];

        double vare = (See - Se * Se / N) / (N - 1.0);
        double vart = (Stt - St * St / N) / (N - 1.0);
        double stde = fmax(sqrt(fmax(vare, 0.0)), EPS);
        double stdt = fmax(sqrt(fmax(vart, 0.0)), EPS);
        double cross = Set - Se * St / N;

        double c = cross / (stde * stdt) / (N + EPS);
        c = fmin(fmax(c, -1.0 + EPS), 1.0 - EPS);
        double d = 1.0 - c;
        loss += d * d;
    }

    red[threadIdx.x] = loss;
    __syncthreads();
    for (int s = 128; s > 0; s >>= 1) {
        if (threadIdx.x < s) red[threadIdx.x] += red[threadIdx.x + s];
        __syncthreads();
    }
    if (threadIdx.x == 0) out[0] = (float)red[0];
}

// ---------------------------------------------------------------------------
extern "C" void kernel_launch(void* const* d_in, const int* in_sizes, int n_in,
                              void* d_out, int out_size)
{
    const float* e_q = (const float*)d_in[0];
    const float* tau = (const float*)d_in[1];
    float* out = (float*)d_out;

    dim3 grid1(ROW_BLOCKS, COL_GROUPS);          // 256 x 2 = 512 blocks
    stats_kernel<<<grid1, THREADS>>>(e_q, tau);

    reduce_kernel<<<(5 * NCOLS + 255) / 256, 256>>>();

    loss_kernel<<<1, 256>>>(out);
}

// round 2
// speedup vs baseline: 1.1366x; 1.1366x over previous
#include <cuda_runtime.h>

// BarlowTwinsLoss: e_q [16384,2048] f32, tau [16384,2048] f32, row-major.
// loss = sum_d (1 - clip(corr_d, -1+eps, 1-eps))^2, corr from column-normalized
// (ddof=1) features. Pure streaming reduction: 256 MB mandatory HBM reads.
//
// R2: kernel1 emits only 320 KB of partials (intra-block reduce), single small
// fused epilogue kernel. Deterministic (no float atomics, fixed-order sums).

#define NROWS 16384
#define NCOLS 2048
#define ROW_CHUNKS 8            // blockIdx.y
#define ROWS_PER_CHUNK (NROWS / ROW_CHUNKS)        // 2048
#define SUBCHUNKS 8             // threadIdx.y
#define ROWS_PER_THREAD (ROWS_PER_CHUNK / SUBCHUNKS) // 256
#define COLS_PER_BLOCK 32       // threadIdx.x
#define COL_BLOCKS (NCOLS / COLS_PER_BLOCK)        // 64

// 5 stats x 8 rowchunks x 2048 cols x 4B = 320 KB static scratch
__device__ float g_partial[5][ROW_CHUNKS][NCOLS];

// ---------------------------------------------------------------------------
// Kernel 1: streaming sufficient statistics.
// Block = 32 cols x 8 row-subchunks (256 threads). Warp = one subchunk row
// across 32 consecutive columns -> each load = exactly one 128B line.
// ---------------------------------------------------------------------------
__global__ void __launch_bounds__(256)
stats_kernel(const float* __restrict__ e, const float* __restrict__ t)
{
    const int colbase = blockIdx.x * COLS_PER_BLOCK;
    const int col     = colbase + threadIdx.x;
    const size_t row0 = (size_t)blockIdx.y * ROWS_PER_CHUNK
                      + (size_t)threadIdx.y * ROWS_PER_THREAD;

    const float* __restrict__ pe = e + row0 * NCOLS + col;
    const float* __restrict__ pt = t + row0 * NCOLS + col;

    float se = 0.f, st = 0.f, ee = 0.f, tt = 0.f, et = 0.f;

    #pragma unroll 8
    for (int r = 0; r < ROWS_PER_THREAD; ++r) {
        float a = pe[(size_t)r * NCOLS];
        float b = pt[(size_t)r * NCOLS];
        se += a;
        st += b;
        ee = fmaf(a, a, ee);
        tt = fmaf(b, b, tt);
        et = fmaf(a, b, et);
    }

    __shared__ float sh[5][SUBCHUNKS][COLS_PER_BLOCK + 1];
    sh[0][threadIdx.y][threadIdx.x] = se;
    sh[1][threadIdx.y][threadIdx.x] = st;
    sh[2][threadIdx.y][threadIdx.x] = ee;
    sh[3][threadIdx.y][threadIdx.x] = tt;
    sh[4][threadIdx.y][threadIdx.x] = et;
    __syncthreads();

    // 160 threads: (stat s, col tx). Fixed-order sum over 8 subchunks.
    const int tid = threadIdx.y * COLS_PER_BLOCK + threadIdx.x;
    if (tid < 5 * COLS_PER_BLOCK) {
        const int s  = tid >> 5;
        const int tx = tid & 31;
        float acc = 0.f;
        #pragma unroll
        for (int k = 0; k < SUBCHUNKS; ++k)
            acc += sh[s][k][tx];
        g_partial[s][blockIdx.y][colbase + tx] = acc;
    }
}

// ---------------------------------------------------------------------------
// Kernel 2: fused reduce + loss. One block, 1024 threads; thread owns 2 cols.
// Reads 320 KB (coalesced), fp64 finalize, deterministic tree reduce.
// ---------------------------------------------------------------------------
__global__ void __launch_bounds__(1024)
loss_kernel(float* __restrict__ out)
{
    const double N   = (double)NROWS;
    const double EPS = 1e-9;
    const int tid = threadIdx.x;

    double loss = 0.0;

    #pragma unroll
    for (int half = 0; half < 2; ++half) {
        const int col = tid + half * 1024;

        // Gather partials first (maximize MLP), then combine in fixed order.
        float p[5][ROW_CHUNKS];
        #pragma unroll
        for (int s = 0; s < 5; ++s)
            #pragma unroll
            for (int rb = 0; rb < ROW_CHUNKS; ++rb)
                p[s][rb] = g_partial[s][rb][col];

        double S[5];
        #pragma unroll
        for (int s = 0; s < 5; ++s) {
            double acc = 0.0;
            #pragma unroll
            for (int rb = 0; rb < ROW_CHUNKS; ++rb)
                acc += (double)p[s][rb];
            S[s] = acc;
        }

        const double Se  = S[0], St = S[1], See = S[2], Stt = S[3], Set = S[4];
        const double vare = (See - Se * Se / N) / (N - 1.0);
        const double vart = (Stt - St * St / N) / (N - 1.0);
        const double stde = fmax(sqrt(fmax(vare, 0.0)), EPS);
        const double stdt = fmax(sqrt(fmax(vart, 0.0)), EPS);
        const double cross = Set - Se * St / N;

        double c = cross / (stde * stdt) / (N + EPS);
        c = fmin(fmax(c, -1.0 + EPS), 1.0 - EPS);
        const double d = 1.0 - c;
        loss += d * d;
    }

    __shared__ double red[1024];
    red[tid] = loss;
    __syncthreads();
    #pragma unroll
    for (int s = 512; s > 0; s >>= 1) {
        if (tid < s) red[tid] += red[tid + s];
        __syncthreads();
    }
    if (tid == 0) out[0] = (float)red[0];
}

// ---------------------------------------------------------------------------
extern "C" void kernel_launch(void* const* d_in, const int* in_sizes, int n_in,
                              void* d_out, int out_size)
{
    const float* e_q = (const float*)d_in[0];
    const float* tau = (const float*)d_in[1];
    float* out = (float*)d_out;

    dim3 block1(COLS_PER_BLOCK, SUBCHUNKS);       // 32 x 8 = 256
    dim3 grid1(COL_BLOCKS, ROW_CHUNKS);           // 64 x 8 = 512 blocks
    stats_kernel<<<grid1, block1>>>(e_q, tau);

    loss_kernel<<<1, 1024>>>(out);
}